// round 3
// baseline (speedup 1.0000x reference)
#include <cuda_runtime.h>
#include <math.h>

// Problem constants
#define NTOK   8192          // B*T = 4*2048
#define DDIM   512
#define NEXP   8
#define HDIM   512
#define NPAIR  (NTOK * 2)    // top-2

// ---- device scratch (allocation-free) ----
__device__ int   g_cnt[NEXP];
__device__ int   g_list[NEXP * NTOK];   // per-expert lists of pair ids (n*2+k)
__device__ float g_w[NPAIR];            // gate weight per pair
__device__ float g_hbuf[NPAIR * HDIM];  // 32 MB hidden activations, indexed by pair id

// ---------------------------------------------------------------------------
// zero: clear output accumulator and expert counters
// ---------------------------------------------------------------------------
__global__ void zero_kernel(float* __restrict__ out) {
    int i = blockIdx.x * blockDim.x + threadIdx.x;
    if (i < NTOK * HDIM) out[i] = 0.0f;
    if (i < NEXP) g_cnt[i] = 0;
}

// ---------------------------------------------------------------------------
// gate: one warp per token. logits = x @ Wg + bg ; top-2 (strict >, matches
// jax.lax.top_k lowest-index tie-break); softmax over the 2 scores; scatter.
// ---------------------------------------------------------------------------
__global__ void gate_kernel(const float* __restrict__ x,
                            const float* __restrict__ Wg,
                            const float* __restrict__ bg) {
    int tid  = blockIdx.x * blockDim.x + threadIdx.x;
    int tok  = tid >> 5;
    int lane = threadIdx.x & 31;
    if (tok >= NTOK) return;

    const float* xr = x + (size_t)tok * DDIM;
    float acc[NEXP];
#pragma unroll
    for (int e = 0; e < NEXP; e++) acc[e] = 0.0f;

    for (int d = lane; d < DDIM; d += 32) {
        float v = xr[d];
        const float* wrow = Wg + d * NEXP;
#pragma unroll
        for (int e = 0; e < NEXP; e++) acc[e] += v * wrow[e];
    }
#pragma unroll
    for (int e = 0; e < NEXP; e++) {
#pragma unroll
        for (int o = 16; o > 0; o >>= 1)
            acc[e] += __shfl_down_sync(0xffffffffu, acc[e], o);
    }

    if (lane == 0) {
        float s[NEXP];
#pragma unroll
        for (int e = 0; e < NEXP; e++) s[e] = acc[e] + bg[e];

        int i0 = 0;
#pragma unroll
        for (int e = 1; e < NEXP; e++) if (s[e] > s[i0]) i0 = e;
        int i1 = -1;
#pragma unroll
        for (int e = 0; e < NEXP; e++) {
            if (e == i0) continue;
            if (i1 < 0 || s[e] > s[i1]) i1 = e;
        }
        // softmax over the two selected scores (s[i0] >= s[i1])
        float w0 = 1.0f / (1.0f + expf(s[i1] - s[i0]));
        float w1 = 1.0f - w0;

        int p0 = tok * 2 + 0;
        int p1 = tok * 2 + 1;
        int slot0 = atomicAdd(&g_cnt[i0], 1);
        g_list[i0 * NTOK + slot0] = p0;
        int slot1 = atomicAdd(&g_cnt[i1], 1);
        g_list[i1 * NTOK + slot1] = p1;
        g_w[p0] = w0;
        g_w[p1] = w1;
    }
}

// ---------------------------------------------------------------------------
// Grouped GEMM, gathered-A, 64x64 tile, BK=16, 256 threads, 4x4 per thread.
// LAYER2=false: h = gelu(x_gathered @ W1[e] + b1[e]) -> g_hbuf[pair]
// LAYER2=true : out[n] += w_pair * (h_gathered @ W2[e] + b2[e])  (atomicAdd)
// ---------------------------------------------------------------------------
template <bool LAYER2>
__global__ void moe_gemm_kernel(const float* __restrict__ x,
                                const float* __restrict__ W1,
                                const float* __restrict__ b1,
                                const float* __restrict__ W2,
                                const float* __restrict__ b2,
                                float* __restrict__ out) {
    const int e   = blockIdx.z;
    const int cnt = g_cnt[e];
    const int m0  = blockIdx.y * 64;
    if (m0 >= cnt) return;
    const int n0 = blockIdx.x * 64;

    __shared__ float As[16][65];  // [k][m], padded
    __shared__ float Bs[16][64];  // [k][n]
    __shared__ int   sIdx[64];

    const int t = threadIdx.x;  // 0..255
    if (t < 64) sIdx[t] = (m0 + t < cnt) ? g_list[e * NTOK + m0 + t] : -1;
    __syncthreads();

    const float* Wmat = LAYER2 ? (W2 + (size_t)e * HDIM * HDIM)
                               : (W1 + (size_t)e * DDIM * HDIM);
    const int KDIM = LAYER2 ? HDIM : DDIM;

    float acc[4][4];
#pragma unroll
    for (int i = 0; i < 4; i++)
#pragma unroll
        for (int j = 0; j < 4; j++) acc[i][j] = 0.0f;

    const int ty = t >> 4;   // 0..15 (row group)
    const int tx = t & 15;   // 0..15 (col group)

    for (int k0 = 0; k0 < KDIM; k0 += 16) {
        // A tile: 64 rows x 16 cols (gathered rows)
#pragma unroll
        for (int i = 0; i < 4; i++) {
            int li = t + i * 256;
            int r  = li >> 4;
            int c  = li & 15;
            int p  = sIdx[r];
            float v = 0.0f;
            if (p >= 0) {
                if (LAYER2) v = g_hbuf[(size_t)p * HDIM + k0 + c];
                else        v = x[(size_t)(p >> 1) * DDIM + k0 + c];
            }
            As[c][r] = v;
        }
        // B tile: 16 rows x 64 cols
#pragma unroll
        for (int i = 0; i < 4; i++) {
            int li = t + i * 256;
            int r  = li >> 6;
            int c  = li & 63;
            Bs[r][c] = Wmat[(size_t)(k0 + r) * HDIM + n0 + c];
        }
        __syncthreads();

#pragma unroll
        for (int k = 0; k < 16; k++) {
            float a[4], b[4];
#pragma unroll
            for (int i = 0; i < 4; i++) a[i] = As[k][ty * 4 + i];
#pragma unroll
            for (int j = 0; j < 4; j++) b[j] = Bs[k][tx * 4 + j];
#pragma unroll
            for (int i = 0; i < 4; i++)
#pragma unroll
                for (int j = 0; j < 4; j++) acc[i][j] += a[i] * b[j];
        }
        __syncthreads();
    }

    // epilogue
#pragma unroll
    for (int i = 0; i < 4; i++) {
        int r = ty * 4 + i;
        int p = sIdx[r];
        if (p < 0) continue;
#pragma unroll
        for (int j = 0; j < 4; j++) {
            int h = n0 + tx * 4 + j;
            if (!LAYER2) {
                float v = acc[i][j] + b1[e * HDIM + h];
                // exact gelu: 0.5*x*(1+erf(x/sqrt(2)))
                v = 0.5f * v * (1.0f + erff(v * 0.70710678118654752f));
                g_hbuf[(size_t)p * HDIM + h] = v;
            } else {
                float v = acc[i][j] + b2[e * HDIM + h];
                v *= g_w[p];
                atomicAdd(&out[(size_t)(p >> 1) * HDIM + h], v);
            }
        }
    }
}

// ---------------------------------------------------------------------------
extern "C" void kernel_launch(void* const* d_in, const int* in_sizes, int n_in,
                              void* d_out, int out_size) {
    const float* x  = (const float*)d_in[0];
    const float* Wg = (const float*)d_in[1];
    const float* bg = (const float*)d_in[2];
    const float* W1 = (const float*)d_in[3];
    const float* b1 = (const float*)d_in[4];
    const float* W2 = (const float*)d_in[5];
    const float* b2 = (const float*)d_in[6];
    float* out = (float*)d_out;

    zero_kernel<<<(NTOK * HDIM + 255) / 256, 256>>>(out);
    gate_kernel<<<NTOK / 8, 256>>>(x, Wg, bg);

    dim3 grid(HDIM / 64, NTOK / 64, NEXP);
    moe_gemm_kernel<false><<<grid, 256>>>(x, W1, b1, W2, b2, out);
    moe_gemm_kernel<true ><<<grid, 256>>>(x, W1, b1, W2, b2, out);
}

// round 6
// speedup vs baseline: 2.1719x; 2.1719x over previous
#include <cuda_runtime.h>
#include <cuda_bf16.h>
#include <math.h>
#include <stdint.h>

// ---------------- problem sizes ----------------
#define NTOK  8192
#define DDIM  512
#define NEXP  8
#define HDIM  512
#define NPAIR (NTOK * 2)

// ---------------- device scratch (allocation-free) ----------------
__device__ int   g_cnt[NEXP];
__device__ int   g_list[NEXP * NTOK];
__device__ float g_w[NPAIR];
__device__ __nv_bfloat16 g_xh[NTOK * DDIM];
__device__ __nv_bfloat16 g_xl[NTOK * DDIM];
__device__ __nv_bfloat16 g_w1h[NEXP * DDIM * HDIM];   // transposed: [e][n][k]
__device__ __nv_bfloat16 g_w1l[NEXP * DDIM * HDIM];
__device__ __nv_bfloat16 g_w2h[NEXP * HDIM * HDIM];
__device__ __nv_bfloat16 g_w2l[NEXP * HDIM * HDIM];
__device__ __nv_bfloat16 g_hh[(size_t)NPAIR * HDIM];
__device__ __nv_bfloat16 g_hl[(size_t)NPAIR * HDIM];

// ---------------- helpers ----------------
__device__ __forceinline__ uint32_t smem_u32(const void* p) {
    uint32_t a;
    asm("{ .reg .u64 t; cvta.to.shared.u64 t, %1; cvt.u32.u64 %0, t; }" : "=r"(a) : "l"(p));
    return a;
}

#define CP16(dst, src, ok) do {                                              \
    int _sz = (ok) ? 16 : 0;                                                 \
    asm volatile("cp.async.cg.shared.global [%0], [%1], 16, %2;"             \
                 :: "r"(dst), "l"(src), "r"(_sz));                           \
} while (0)
#define CP_COMMIT() asm volatile("cp.async.commit_group;" ::: "memory")
#define CP_WAIT(n)  asm volatile("cp.async.wait_group %0;" :: "n"(n) : "memory")

#define LDSM_X4(r0, r1, r2, r3, a)                                           \
    asm volatile("ldmatrix.sync.aligned.m8n8.x4.shared.b16 {%0,%1,%2,%3}, [%4];" \
                 : "=r"(r0), "=r"(r1), "=r"(r2), "=r"(r3) : "r"(a))

#define MMA16816(c, A, B)                                                    \
    asm volatile("mma.sync.aligned.m16n8k16.row.col.f32.bf16.bf16.f32 "      \
        "{%0,%1,%2,%3}, {%4,%5,%6,%7}, {%8,%9}, {%0,%1,%2,%3};"              \
        : "+f"((c)[0]), "+f"((c)[1]), "+f"((c)[2]), "+f"((c)[3])             \
        : "r"((A)[0]), "r"((A)[1]), "r"((A)[2]), "r"((A)[3]),                \
          "r"((B)[0]), "r"((B)[1]))

// ---------------------------------------------------------------------------
// zero: clear output and expert counters
// ---------------------------------------------------------------------------
__global__ void zero_kernel(float* __restrict__ out) {
    int i = blockIdx.x * blockDim.x + threadIdx.x;
    if (i < NTOK * HDIM) out[i] = 0.0f;
    if (i < NEXP) g_cnt[i] = 0;
}

// ---------------------------------------------------------------------------
// gate: one warp per token, fp32 exact, top-2 with jax tie-break semantics
// ---------------------------------------------------------------------------
__global__ void gate_kernel(const float* __restrict__ x,
                            const float* __restrict__ Wg,
                            const float* __restrict__ bg) {
    int tid  = blockIdx.x * blockDim.x + threadIdx.x;
    int tok  = tid >> 5;
    int lane = threadIdx.x & 31;
    if (tok >= NTOK) return;

    const float* xr = x + (size_t)tok * DDIM;
    float acc[NEXP];
#pragma unroll
    for (int e = 0; e < NEXP; e++) acc[e] = 0.0f;
    for (int d = lane; d < DDIM; d += 32) {
        float v = xr[d];
        const float* wr = Wg + d * NEXP;
#pragma unroll
        for (int e = 0; e < NEXP; e++) acc[e] += v * wr[e];
    }
#pragma unroll
    for (int e = 0; e < NEXP; e++)
#pragma unroll
        for (int o = 16; o > 0; o >>= 1)
            acc[e] += __shfl_down_sync(0xffffffffu, acc[e], o);

    if (lane == 0) {
        float s[NEXP];
#pragma unroll
        for (int e = 0; e < NEXP; e++) s[e] = acc[e] + bg[e];
        int i0 = 0;
#pragma unroll
        for (int e = 1; e < NEXP; e++) if (s[e] > s[i0]) i0 = e;
        int i1 = -1;
#pragma unroll
        for (int e = 0; e < NEXP; e++) {
            if (e == i0) continue;
            if (i1 < 0 || s[e] > s[i1]) i1 = e;
        }
        float w0 = 1.0f / (1.0f + expf(s[i1] - s[i0]));
        float w1 = 1.0f - w0;
        int p0 = tok * 2, p1 = tok * 2 + 1;
        int s0 = atomicAdd(&g_cnt[i0], 1); g_list[i0 * NTOK + s0] = p0;
        int s1 = atomicAdd(&g_cnt[i1], 1); g_list[i1 * NTOK + s1] = p1;
        g_w[p0] = w0; g_w[p1] = w1;
    }
}

// ---------------------------------------------------------------------------
// split_x: fp32 -> bf16 hi/lo
// ---------------------------------------------------------------------------
__global__ void split_x_kernel(const float* __restrict__ x) {
    int i = blockIdx.x * blockDim.x + threadIdx.x;
    if (i >= NTOK * DDIM / 4) return;
    float4 v = ((const float4*)x)[i];
    float f[4] = {v.x, v.y, v.z, v.w};
#pragma unroll
    for (int j = 0; j < 4; j++) {
        __nv_bfloat16 h = __float2bfloat16(f[j]);
        g_xh[i * 4 + j] = h;
        g_xl[i * 4 + j] = __float2bfloat16(f[j] - __bfloat162float(h));
    }
}

// ---------------------------------------------------------------------------
// prep_w: transpose W[e][k][n] -> Wt[e][n][k], split to bf16 hi/lo
// ---------------------------------------------------------------------------
__global__ void prep_w_kernel(const float* __restrict__ W1,
                              const float* __restrict__ W2) {
    __shared__ float tile[32][33];
    int m = blockIdx.z;
    size_t off = (size_t)(m & 7) * 512 * 512;
    const float* W = (m < 8) ? (W1 + off) : (W2 + off);
    __nv_bfloat16* oh = (m < 8) ? (g_w1h + off) : (g_w2h + off);
    __nv_bfloat16* ol = (m < 8) ? (g_w1l + off) : (g_w2l + off);

    int k0 = blockIdx.y * 32, n0 = blockIdx.x * 32;
    int tx = threadIdx.x, ty0 = threadIdx.y;  // (32, 8)
#pragma unroll
    for (int i = 0; i < 4; i++) {
        int ty = ty0 + i * 8;
        tile[ty][tx] = W[(size_t)(k0 + ty) * 512 + n0 + tx];
    }
    __syncthreads();
#pragma unroll
    for (int i = 0; i < 4; i++) {
        int ty = ty0 + i * 8;
        float v = tile[tx][ty];  // = W[k0+tx][n0+ty]
        __nv_bfloat16 h = __float2bfloat16(v);
        size_t o = (size_t)(n0 + ty) * 512 + (k0 + tx);
        oh[o] = h;
        ol[o] = __float2bfloat16(v - __bfloat162float(h));
    }
}

// ---------------------------------------------------------------------------
// grouped split-bf16 HMMA GEMM (mma.sync m16n8k16).
// CTA tile 128x128, K chunks of 64 (128B rows), double-buffered cp.async.
// 8 warps in 2x4 (M x N); each warp computes 64x32.
// Stage layout (64KB): Ah | Al | Bh | Bl, each 128 rows x 128B, XOR-swizzled.
// ---------------------------------------------------------------------------
#define STG_BASE 1024
#define STG_SIZE 65536
#define OFF_AL   16384
#define OFF_BH   32768
#define OFF_BL   49152
#define SMEM_TOT (STG_BASE + 2 * STG_SIZE)

template <bool L2K>
__global__ void __launch_bounds__(256, 1)
moe_hmma_kernel(const float* __restrict__ b1, const float* __restrict__ b2,
                float* __restrict__ out) {
    const int e   = blockIdx.z;
    const int cnt = g_cnt[e];
    const int m0  = blockIdx.y * 128;
    if (m0 >= cnt) return;
    const int n0 = blockIdx.x * 128;

    extern __shared__ char smem[];
    const uint32_t sb = smem_u32(smem);
    int*   sIdx  = (int*)(smem);
    float* sbias = (float*)(smem + 512);

    const int tid  = threadIdx.x;
    const int wid  = tid >> 5;
    const int lane = tid & 31;

    if (tid < 128) {
        sIdx[tid]  = (m0 + tid < cnt) ? g_list[e * NTOK + m0 + tid] : -1;
        sbias[tid] = (L2K ? b2 : b1)[e * HDIM + n0 + tid];
    }
    __syncthreads();

    // ---- per-thread load lanes: row = tid>>1 (0..127), half = tid&1 ----
    const int lrow = tid >> 1;
    const int half = tid & 1;
    const int p    = sIdx[lrow];
    const bool okA = (p >= 0);

    const uint4* arh;
    const uint4* arl;
    {
        size_t ab = okA ? (L2K ? ((size_t)p * HDIM) : ((size_t)(p >> 1) * DDIM)) : 0;
        arh = (const uint4*)((L2K ? g_hh : g_xh) + ab);
        arl = (const uint4*)((L2K ? g_hl : g_xl) + ab);
    }
    const size_t bb = ((size_t)e * HDIM + n0 + lrow) * 512;
    const uint4* brh = (const uint4*)((L2K ? g_w2h : g_w1h) + bb);
    const uint4* brl = (const uint4*)((L2K ? g_w2l : g_w1l) + bb);

    // swizzled in-stage byte offsets for this thread's 4 chunks
    uint32_t swo[4];
#pragma unroll
    for (int i = 0; i < 4; i++) {
        int ch = half * 4 + i;
        swo[i] = (uint32_t)lrow * 128 + (uint32_t)((ch ^ (lrow & 7)) * 16);
    }

    // ---- accumulators ----
    float acc[4][4][4];
#pragma unroll
    for (int mt = 0; mt < 4; mt++)
#pragma unroll
        for (int nt = 0; nt < 4; nt++)
#pragma unroll
            for (int j = 0; j < 4; j++) acc[mt][nt][j] = 0.0f;

    // warp tiling
    const int wm = wid >> 2;          // 0..1
    const int wn = wid & 3;           // 0..3
    // ldmatrix lane geometry (row&7 == lane&7 for all our tiles)
    const int lq = lane >> 3;         // quadrant
    const int lr = lane & 7;
    const int aRow0 = wm * 64 + lr + 8 * (lq & 1);   // + mt*16
    const int aCh0  = lq >> 1;                        // + k16*2
    const int bRow0 = wn * 32 + (lq >> 1) * 8 + lr;  // + bpair*16
    const int bCh0  = lq & 1;                         // + k16*2
    const uint32_t swzx = (uint32_t)(lr) * 16;        // xor on chunk*16

    // ---- issue loads for a stage ----
    auto load_stage = [&](int c, int s) {
        uint32_t base = sb + STG_BASE + (uint32_t)s * STG_SIZE;
        int kq = c * 8;
#pragma unroll
        for (int i = 0; i < 4; i++) {
            int ch = half * 4 + i;
            uint32_t d = base + swo[i];
            CP16(d,          arh + kq + ch, okA);
            CP16(d + OFF_AL, arl + kq + ch, okA);
            CP16(d + OFF_BH, brh + kq + ch, true);
            CP16(d + OFF_BL, brl + kq + ch, true);
        }
        CP_COMMIT();
    };

    load_stage(0, 0);

    for (int c = 0; c < 8; c++) {
        const int s = c & 1;
        if (c + 1 < 8) load_stage(c + 1, s ^ 1);
        if (c + 1 < 8) CP_WAIT(1); else CP_WAIT(0);
        __syncthreads();

        const uint32_t stg = sb + STG_BASE + (uint32_t)s * STG_SIZE;
#pragma unroll
        for (int k16 = 0; k16 < 4; k16++) {
            // B fragments: 4 n-tiles x {h,l}, loaded as 2 x4 per array
            uint32_t bh[8], bl[8];
#pragma unroll
            for (int bp = 0; bp < 2; bp++) {
                uint32_t ro = (uint32_t)(bRow0 + bp * 16) * 128;
                uint32_t co = (uint32_t)((k16 * 2 + bCh0) * 16) ^ swzx;
                uint32_t ad = stg + OFF_BH + ro + co;
                LDSM_X4(bh[bp*4+0], bh[bp*4+1], bh[bp*4+2], bh[bp*4+3], ad);
                ad = stg + OFF_BL + ro + co;
                LDSM_X4(bl[bp*4+0], bl[bp*4+1], bl[bp*4+2], bl[bp*4+3], ad);
            }
#pragma unroll
            for (int mt = 0; mt < 4; mt++) {
                uint32_t ah[4], al[4];
                uint32_t ro = (uint32_t)(aRow0 + mt * 16) * 128;
                uint32_t co = (uint32_t)((k16 * 2 + aCh0) * 16) ^ swzx;
                LDSM_X4(ah[0], ah[1], ah[2], ah[3], stg + ro + co);
                LDSM_X4(al[0], al[1], al[2], al[3], stg + OFF_AL + ro + co);
#pragma unroll
                for (int nt = 0; nt < 4; nt++) {
                    MMA16816(acc[mt][nt], ah, bh + nt * 2);
                    MMA16816(acc[mt][nt], ah, bl + nt * 2);
                    MMA16816(acc[mt][nt], al, bh + nt * 2);
                }
            }
        }
        __syncthreads();
    }

    // ---- epilogue ----
    const int eg  = lane >> 2;   // group id (row within tile)
    const int tig = lane & 3;
#pragma unroll
    for (int mt = 0; mt < 4; mt++) {
#pragma unroll
        for (int hrow = 0; hrow < 2; hrow++) {
            const int rl = wm * 64 + mt * 16 + eg + hrow * 8;
            const int pp = sIdx[rl];
            if (pp < 0) continue;
            const float gw = L2K ? g_w[pp] : 0.0f;
#pragma unroll
            for (int nt = 0; nt < 4; nt++) {
                const int cl = wn * 32 + nt * 8 + tig * 2;
                float v0 = acc[mt][nt][hrow * 2 + 0] + sbias[cl];
                float v1 = acc[mt][nt][hrow * 2 + 1] + sbias[cl + 1];
                if (!L2K) {
                    v0 = 0.5f * v0 * (1.0f + erff(v0 * 0.70710678118654752f));
                    v1 = 0.5f * v1 * (1.0f + erff(v1 * 0.70710678118654752f));
                    __nv_bfloat16 h0 = __float2bfloat16(v0);
                    __nv_bfloat16 h1 = __float2bfloat16(v1);
                    __nv_bfloat16 l0 = __float2bfloat16(v0 - __bfloat162float(h0));
                    __nv_bfloat16 l1 = __float2bfloat16(v1 - __bfloat162float(h1));
                    size_t o = (size_t)pp * HDIM + n0 + cl;
                    *(__nv_bfloat162*)(g_hh + o) = __nv_bfloat162(h0, h1);
                    *(__nv_bfloat162*)(g_hl + o) = __nv_bfloat162(l0, l1);
                } else {
                    size_t o = (size_t)(pp >> 1) * HDIM + n0 + cl;
                    atomicAdd(&out[o],     v0 * gw);
                    atomicAdd(&out[o + 1], v1 * gw);
                }
            }
        }
    }
}

// ---------------------------------------------------------------------------
extern "C" void kernel_launch(void* const* d_in, const int* in_sizes, int n_in,
                              void* d_out, int out_size) {
    const float* x  = (const float*)d_in[0];
    const float* Wg = (const float*)d_in[1];
    const float* bg = (const float*)d_in[2];
    const float* W1 = (const float*)d_in[3];
    const float* b1 = (const float*)d_in[4];
    const float* W2 = (const float*)d_in[5];
    const float* b2 = (const float*)d_in[6];
    float* out = (float*)d_out;

    cudaFuncSetAttribute(moe_hmma_kernel<false>,
                         cudaFuncAttributeMaxDynamicSharedMemorySize, SMEM_TOT);
    cudaFuncSetAttribute(moe_hmma_kernel<true>,
                         cudaFuncAttributeMaxDynamicSharedMemorySize, SMEM_TOT);

    zero_kernel<<<(NTOK * HDIM + 255) / 256, 256>>>(out);
    gate_kernel<<<NTOK / 8, 256>>>(x, Wg, bg);
    split_x_kernel<<<(NTOK * DDIM / 4 + 255) / 256, 256>>>(x);
    prep_w_kernel<<<dim3(16, 16, 16), dim3(32, 8)>>>(W1, W2);

    dim3 grid(HDIM / 128, NTOK / 128, NEXP);
    moe_hmma_kernel<false><<<grid, 256, SMEM_TOT>>>(b1, b2, out);
    moe_hmma_kernel<true ><<<grid, 256, SMEM_TOT>>>(b1, b2, out);
}

// round 7
// speedup vs baseline: 2.5511x; 1.1746x over previous
#include <cuda_runtime.h>
#include <cuda_bf16.h>
#include <math.h>
#include <stdint.h>

// ---------------- problem sizes ----------------
#define NTOK  8192
#define DDIM  512
#define NEXP  8
#define HDIM  512
#define NPAIR (NTOK * 2)

// ---------------- device scratch (allocation-free) ----------------
__device__ int   g_cnt[NEXP];
__device__ int   g_list[NEXP * NTOK];
__device__ float g_w[NPAIR];
__device__ __nv_bfloat16 g_xh[NTOK * DDIM];
__device__ __nv_bfloat16 g_xl[NTOK * DDIM];
__device__ __nv_bfloat16 g_w1h[NEXP * DDIM * HDIM];   // transposed: [e][n][k]
__device__ __nv_bfloat16 g_w1l[NEXP * DDIM * HDIM];
__device__ __nv_bfloat16 g_w2h[NEXP * HDIM * HDIM];
__device__ __nv_bfloat16 g_w2l[NEXP * HDIM * HDIM];
__device__ __nv_bfloat16 g_hh[(size_t)NPAIR * HDIM];
__device__ __nv_bfloat16 g_hl[(size_t)NPAIR * HDIM];

// ---------------- helpers ----------------
__device__ __forceinline__ uint32_t smem_u32(const void* p) {
    uint32_t a;
    asm("{ .reg .u64 t; cvta.to.shared.u64 t, %1; cvt.u32.u64 %0, t; }" : "=r"(a) : "l"(p));
    return a;
}

#define CP16(dst, src, ok) do {                                              \
    int _sz = (ok) ? 16 : 0;                                                 \
    asm volatile("cp.async.cg.shared.global [%0], [%1], 16, %2;"             \
                 :: "r"(dst), "l"(src), "r"(_sz));                           \
} while (0)
#define CP_COMMIT() asm volatile("cp.async.commit_group;" ::: "memory")
#define CP_WAIT(n)  asm volatile("cp.async.wait_group %0;" :: "n"(n) : "memory")

#define LDSM_X4(r0, r1, r2, r3, a)                                           \
    asm volatile("ldmatrix.sync.aligned.m8n8.x4.shared.b16 {%0,%1,%2,%3}, [%4];" \
                 : "=r"(r0), "=r"(r1), "=r"(r2), "=r"(r3) : "r"(a))

#define MMA16816(c, A, B)                                                    \
    asm volatile("mma.sync.aligned.m16n8k16.row.col.f32.bf16.bf16.f32 "      \
        "{%0,%1,%2,%3}, {%4,%5,%6,%7}, {%8,%9}, {%0,%1,%2,%3};"              \
        : "+f"((c)[0]), "+f"((c)[1]), "+f"((c)[2]), "+f"((c)[3])             \
        : "r"((A)[0]), "r"((A)[1]), "r"((A)[2]), "r"((A)[3]),                \
          "r"((B)[0]), "r"((B)[1]))

// ---------------------------------------------------------------------------
// split_x + zero (fused): fp32 -> bf16 hi/lo, zero out, clear counters
// ---------------------------------------------------------------------------
__global__ void split_x_zero_kernel(const float* __restrict__ x,
                                    float* __restrict__ out) {
    int i = blockIdx.x * blockDim.x + threadIdx.x;
    if (i >= NTOK * DDIM / 4) return;
    ((float4*)out)[i] = make_float4(0.f, 0.f, 0.f, 0.f);  // NTOK*HDIM/4 == NTOK*DDIM/4
    if (i < NEXP) g_cnt[i] = 0;
    float4 v = ((const float4*)x)[i];
    float f[4] = {v.x, v.y, v.z, v.w};
#pragma unroll
    for (int j = 0; j < 4; j++) {
        __nv_bfloat16 h = __float2bfloat16(f[j]);
        g_xh[i * 4 + j] = h;
        g_xl[i * 4 + j] = __float2bfloat16(f[j] - __bfloat162float(h));
    }
}

// ---------------------------------------------------------------------------
// gate: one warp per token, fp32 exact, top-2 with jax tie-break semantics
// ---------------------------------------------------------------------------
__global__ void gate_kernel(const float* __restrict__ x,
                            const float* __restrict__ Wg,
                            const float* __restrict__ bg) {
    int tid  = blockIdx.x * blockDim.x + threadIdx.x;
    int tok  = tid >> 5;
    int lane = threadIdx.x & 31;
    if (tok >= NTOK) return;

    const float* xr = x + (size_t)tok * DDIM;
    float acc[NEXP];
#pragma unroll
    for (int e = 0; e < NEXP; e++) acc[e] = 0.0f;
    for (int d = lane; d < DDIM; d += 32) {
        float v = xr[d];
        const float* wr = Wg + d * NEXP;
#pragma unroll
        for (int e = 0; e < NEXP; e++) acc[e] += v * wr[e];
    }
#pragma unroll
    for (int e = 0; e < NEXP; e++)
#pragma unroll
        for (int o = 16; o > 0; o >>= 1)
            acc[e] += __shfl_down_sync(0xffffffffu, acc[e], o);

    if (lane == 0) {
        float s[NEXP];
#pragma unroll
        for (int e = 0; e < NEXP; e++) s[e] = acc[e] + bg[e];
        int i0 = 0;
#pragma unroll
        for (int e = 1; e < NEXP; e++) if (s[e] > s[i0]) i0 = e;
        int i1 = -1;
#pragma unroll
        for (int e = 0; e < NEXP; e++) {
            if (e == i0) continue;
            if (i1 < 0 || s[e] > s[i1]) i1 = e;
        }
        float w0 = 1.0f / (1.0f + expf(s[i1] - s[i0]));
        float w1 = 1.0f - w0;
        int p0 = tok * 2, p1 = tok * 2 + 1;
        int s0 = atomicAdd(&g_cnt[i0], 1); g_list[i0 * NTOK + s0] = p0;
        int s1 = atomicAdd(&g_cnt[i1], 1); g_list[i1 * NTOK + s1] = p1;
        g_w[p0] = w0; g_w[p1] = w1;
    }
}

// ---------------------------------------------------------------------------
// prep_w: transpose W[e][k][n] -> Wt[e][n][k], split to bf16 hi/lo
// ---------------------------------------------------------------------------
__global__ void prep_w_kernel(const float* __restrict__ W1,
                              const float* __restrict__ W2) {
    __shared__ float tile[32][33];
    int m = blockIdx.z;
    size_t off = (size_t)(m & 7) * 512 * 512;
    const float* W = (m < 8) ? (W1 + off) : (W2 + off);
    __nv_bfloat16* oh = (m < 8) ? (g_w1h + off) : (g_w2h + off);
    __nv_bfloat16* ol = (m < 8) ? (g_w1l + off) : (g_w2l + off);

    int k0 = blockIdx.y * 32, n0 = blockIdx.x * 32;
    int tx = threadIdx.x, ty0 = threadIdx.y;  // (32, 8)
#pragma unroll
    for (int i = 0; i < 4; i++) {
        int ty = ty0 + i * 8;
        tile[ty][tx] = W[(size_t)(k0 + ty) * 512 + n0 + tx];
    }
    __syncthreads();
#pragma unroll
    for (int i = 0; i < 4; i++) {
        int ty = ty0 + i * 8;
        float v = tile[tx][ty];  // = W[k0+tx][n0+ty]
        __nv_bfloat16 h = __float2bfloat16(v);
        size_t o = (size_t)(n0 + ty) * 512 + (k0 + tx);
        oh[o] = h;
        ol[o] = __float2bfloat16(v - __bfloat162float(h));
    }
}

// ---------------------------------------------------------------------------
// grouped split-bf16 HMMA GEMM (mma.sync m16n8k16).
// CTA tile 128x64, K chunks of 64 (128B rows), double-buffered cp.async.
// Stage (48KB): Ah(16K) | Al(16K) | Bh(8K) | Bl(8K); 2 stages = 96KB -> 2 CTA/SM.
// 8 warps in 4x2 (M x N); each warp computes 32x32.
// ---------------------------------------------------------------------------
#define STG_BASE 1024
#define STG_SIZE 49152
#define OFF_AL   16384
#define OFF_BH   32768
#define OFF_BL   40960
#define SMEM_TOT (STG_BASE + 2 * STG_SIZE)

template <bool L2K>
__global__ void __launch_bounds__(256, 2)
moe_hmma_kernel(const float* __restrict__ b1, const float* __restrict__ b2,
                float* __restrict__ out) {
    const int e   = blockIdx.z;
    const int cnt = g_cnt[e];
    const int m0  = blockIdx.y * 128;
    if (m0 >= cnt) return;
    const int n0 = blockIdx.x * 64;

    extern __shared__ char smem[];
    const uint32_t sb = smem_u32(smem);
    int*   sIdx  = (int*)(smem);
    float* sbias = (float*)(smem + 512);

    const int tid  = threadIdx.x;
    const int wid  = tid >> 5;
    const int lane = tid & 31;

    if (tid < 128) sIdx[tid] = (m0 + tid < cnt) ? g_list[e * NTOK + m0 + tid] : -1;
    if (tid < 64)  sbias[tid] = (L2K ? b2 : b1)[e * HDIM + n0 + tid];
    __syncthreads();

    // ---- A load lanes: row = tid>>1 (0..127), half = tid&1 (4 chunks each) ----
    const int lrow = tid >> 1;
    const int half = tid & 1;
    const int p    = sIdx[lrow];
    const bool okA = (p >= 0);

    const uint4* arh;
    const uint4* arl;
    {
        size_t ab = okA ? (L2K ? ((size_t)p * HDIM) : ((size_t)(p >> 1) * DDIM)) : 0;
        arh = (const uint4*)((L2K ? g_hh : g_xh) + ab);
        arl = (const uint4*)((L2K ? g_hl : g_xl) + ab);
    }
    // ---- B load lanes: row = tid>>2 (0..63), 2 chunks (qc*2, qc*2+1) ----
    const int brow = tid >> 2;
    const int qc   = tid & 3;
    const size_t bb = ((size_t)e * HDIM + n0 + brow) * 512;
    const uint4* brh = (const uint4*)((L2K ? g_w2h : g_w1h) + bb);
    const uint4* brl = (const uint4*)((L2K ? g_w2l : g_w1l) + bb);

    uint32_t swoA[4], swoB[2];
#pragma unroll
    for (int i = 0; i < 4; i++) {
        int ch = half * 4 + i;
        swoA[i] = (uint32_t)lrow * 128 + (uint32_t)((ch ^ (lrow & 7)) * 16);
    }
#pragma unroll
    for (int i = 0; i < 2; i++) {
        int ch = qc * 2 + i;
        swoB[i] = (uint32_t)brow * 128 + (uint32_t)((ch ^ (brow & 7)) * 16);
    }

    // ---- accumulators: warp tile 32x32 -> 2 m-tiles x 4 n-tiles ----
    float acc[2][4][4];
#pragma unroll
    for (int mt = 0; mt < 2; mt++)
#pragma unroll
        for (int nt = 0; nt < 4; nt++)
#pragma unroll
            for (int j = 0; j < 4; j++) acc[mt][nt][j] = 0.0f;

    const int wm = wid >> 1;          // 0..3
    const int wn = wid & 1;           // 0..1
    const int lq = lane >> 3;
    const int lr = lane & 7;
    const int aRow0 = wm * 32 + lr + 8 * (lq & 1);
    const int aCh0  = lq >> 1;
    const int bRow0 = wn * 32 + (lq >> 1) * 8 + lr;
    const int bCh0  = lq & 1;
    const uint32_t swzx = (uint32_t)(lr) * 16;

    auto load_stage = [&](int c, int s) {
        uint32_t base = sb + STG_BASE + (uint32_t)s * STG_SIZE;
        int kq = c * 8;
#pragma unroll
        for (int i = 0; i < 4; i++) {
            int ch = half * 4 + i;
            uint32_t d = base + swoA[i];
            CP16(d,          arh + kq + ch, okA);
            CP16(d + OFF_AL, arl + kq + ch, okA);
        }
#pragma unroll
        for (int i = 0; i < 2; i++) {
            int ch = qc * 2 + i;
            uint32_t d = base + swoB[i];
            CP16(d + OFF_BH, brh + kq + ch, true);
            CP16(d + OFF_BL, brl + kq + ch, true);
        }
        CP_COMMIT();
    };

    load_stage(0, 0);

    for (int c = 0; c < 8; c++) {
        const int s = c & 1;
        if (c + 1 < 8) load_stage(c + 1, s ^ 1);
        if (c + 1 < 8) CP_WAIT(1); else CP_WAIT(0);
        __syncthreads();

        const uint32_t stg = sb + STG_BASE + (uint32_t)s * STG_SIZE;
#pragma unroll
        for (int k16 = 0; k16 < 4; k16++) {
            uint32_t bh[8], bl[8];
#pragma unroll
            for (int bp = 0; bp < 2; bp++) {
                uint32_t ro = (uint32_t)(bRow0 + bp * 16) * 128;
                uint32_t co = (uint32_t)((k16 * 2 + bCh0) * 16) ^ swzx;
                uint32_t ad = stg + OFF_BH + ro + co;
                LDSM_X4(bh[bp*4+0], bh[bp*4+1], bh[bp*4+2], bh[bp*4+3], ad);
                ad = stg + OFF_BL + ro + co;
                LDSM_X4(bl[bp*4+0], bl[bp*4+1], bl[bp*4+2], bl[bp*4+3], ad);
            }
#pragma unroll
            for (int mt = 0; mt < 2; mt++) {
                uint32_t ah[4], al[4];
                uint32_t ro = (uint32_t)(aRow0 + mt * 16) * 128;
                uint32_t co = (uint32_t)((k16 * 2 + aCh0) * 16) ^ swzx;
                LDSM_X4(ah[0], ah[1], ah[2], ah[3], stg + ro + co);
                LDSM_X4(al[0], al[1], al[2], al[3], stg + OFF_AL + ro + co);
#pragma unroll
                for (int nt = 0; nt < 4; nt++) {
                    MMA16816(acc[mt][nt], ah, bh + nt * 2);
                    MMA16816(acc[mt][nt], ah, bl + nt * 2);
                    MMA16816(acc[mt][nt], al, bh + nt * 2);
                }
            }
        }
        __syncthreads();
    }

    // ---- epilogue ----
    const int eg  = lane >> 2;
    const int tig = lane & 3;
#pragma unroll
    for (int mt = 0; mt < 2; mt++) {
#pragma unroll
        for (int hrow = 0; hrow < 2; hrow++) {
            const int rl = wm * 32 + mt * 16 + eg + hrow * 8;
            const int pp = sIdx[rl];
            if (pp < 0) continue;
            const float gw = L2K ? g_w[pp] : 0.0f;
#pragma unroll
            for (int nt = 0; nt < 4; nt++) {
                const int cl = wn * 32 + nt * 8 + tig * 2;
                float v0 = acc[mt][nt][hrow * 2 + 0] + sbias[cl];
                float v1 = acc[mt][nt][hrow * 2 + 1] + sbias[cl + 1];
                if (!L2K) {
                    v0 = 0.5f * v0 * (1.0f + erff(v0 * 0.70710678118654752f));
                    v1 = 0.5f * v1 * (1.0f + erff(v1 * 0.70710678118654752f));
                    __nv_bfloat16 h0 = __float2bfloat16(v0);
                    __nv_bfloat16 h1 = __float2bfloat16(v1);
                    __nv_bfloat16 l0 = __float2bfloat16(v0 - __bfloat162float(h0));
                    __nv_bfloat16 l1 = __float2bfloat16(v1 - __bfloat162float(h1));
                    size_t o = (size_t)pp * HDIM + n0 + cl;
                    *(__nv_bfloat162*)(g_hh + o) = __nv_bfloat162(h0, h1);
                    *(__nv_bfloat162*)(g_hl + o) = __nv_bfloat162(l0, l1);
                } else {
                    size_t o = (size_t)(pp >> 1) * HDIM + n0 + cl;
                    atomicAdd(&out[o],     v0 * gw);
                    atomicAdd(&out[o + 1], v1 * gw);
                }
            }
        }
    }
}

// ---------------------------------------------------------------------------
extern "C" void kernel_launch(void* const* d_in, const int* in_sizes, int n_in,
                              void* d_out, int out_size) {
    const float* x  = (const float*)d_in[0];
    const float* Wg = (const float*)d_in[1];
    const float* bg = (const float*)d_in[2];
    const float* W1 = (const float*)d_in[3];
    const float* b1 = (const float*)d_in[4];
    const float* W2 = (const float*)d_in[5];
    const float* b2 = (const float*)d_in[6];
    float* out = (float*)d_out;

    cudaFuncSetAttribute(moe_hmma_kernel<false>,
                         cudaFuncAttributeMaxDynamicSharedMemorySize, SMEM_TOT);
    cudaFuncSetAttribute(moe_hmma_kernel<true>,
                         cudaFuncAttributeMaxDynamicSharedMemorySize, SMEM_TOT);

    split_x_zero_kernel<<<(NTOK * DDIM / 4 + 255) / 256, 256>>>(x, out);
    gate_kernel<<<NTOK / 8, 256>>>(x, Wg, bg);
    prep_w_kernel<<<dim3(16, 16, 16), dim3(32, 8)>>>(W1, W2);

    dim3 grid(HDIM / 64, NTOK / 128, NEXP);
    moe_hmma_kernel<false><<<grid, 256, SMEM_TOT>>>(b1, b2, out);
    moe_hmma_kernel<true ><<<grid, 256, SMEM_TOT>>>(b1, b2, out);
}

// round 8
// speedup vs baseline: 2.9698x; 1.1641x over previous
#include <cuda_runtime.h>
#include <cuda_bf16.h>
#include <math.h>
#include <stdint.h>

// ---------------- problem sizes ----------------
#define NTOK  8192
#define DDIM  512
#define NEXP  8
#define HDIM  512
#define NPAIR (NTOK * 2)

// ---------------- device scratch (allocation-free) ----------------
__device__ int   g_cnt[NEXP];
__device__ int   g_list[NEXP * NTOK];
__device__ float g_w[NPAIR];
__device__ __nv_bfloat16 g_xh[NTOK * DDIM];
__device__ __nv_bfloat16 g_xl[NTOK * DDIM];
__device__ __nv_bfloat16 g_w1h[NEXP * DDIM * HDIM];   // transposed: [e][n][k]
__device__ __nv_bfloat16 g_w1l[NEXP * DDIM * HDIM];
__device__ __nv_bfloat16 g_w2h[NEXP * HDIM * HDIM];
__device__ __nv_bfloat16 g_w2l[NEXP * HDIM * HDIM];
__device__ __nv_bfloat16 g_hh[(size_t)NPAIR * HDIM];
__device__ __nv_bfloat16 g_hl[(size_t)NPAIR * HDIM];

// ---------------- helpers ----------------
__device__ __forceinline__ uint32_t smem_u32(const void* p) {
    uint32_t a;
    asm("{ .reg .u64 t; cvta.to.shared.u64 t, %1; cvt.u32.u64 %0, t; }" : "=r"(a) : "l"(p));
    return a;
}

#define CP16(dst, src, ok) do {                                              \
    int _sz = (ok) ? 16 : 0;                                                 \
    asm volatile("cp.async.cg.shared.global [%0], [%1], 16, %2;"             \
                 :: "r"(dst), "l"(src), "r"(_sz));                           \
} while (0)
#define CP_COMMIT() asm volatile("cp.async.commit_group;" ::: "memory")
#define CP_WAIT(n)  asm volatile("cp.async.wait_group %0;" :: "n"(n) : "memory")

#define LDSM_X4(r0, r1, r2, r3, a)                                           \
    asm volatile("ldmatrix.sync.aligned.m8n8.x4.shared.b16 {%0,%1,%2,%3}, [%4];" \
                 : "=r"(r0), "=r"(r1), "=r"(r2), "=r"(r3) : "r"(a))

#define MMA16816(c, A, B)                                                    \
    asm volatile("mma.sync.aligned.m16n8k16.row.col.f32.bf16.bf16.f32 "      \
        "{%0,%1,%2,%3}, {%4,%5,%6,%7}, {%8,%9}, {%0,%1,%2,%3};"              \
        : "+f"((c)[0]), "+f"((c)[1]), "+f"((c)[2]), "+f"((c)[3])             \
        : "r"((A)[0]), "r"((A)[1]), "r"((A)[2]), "r"((A)[3]),                \
          "r"((B)[0]), "r"((B)[1]))

// ---------------------------------------------------------------------------
// prep_w: transpose W[e][k][n] -> Wt[e][n][k], split to bf16 hi/lo.
// Also zeroes g_cnt (block (0,0,0)) -- runs before the gate kernel.
// ---------------------------------------------------------------------------
__global__ void prep_w_kernel(const float* __restrict__ W1,
                              const float* __restrict__ W2) {
    __shared__ float tile[32][33];
    if (blockIdx.x == 0 && blockIdx.y == 0 && blockIdx.z == 0 &&
        threadIdx.y == 0 && threadIdx.x < NEXP)
        g_cnt[threadIdx.x] = 0;

    int m = blockIdx.z;
    size_t off = (size_t)(m & 7) * 512 * 512;
    const float* W = (m < 8) ? (W1 + off) : (W2 + off);
    __nv_bfloat16* oh = (m < 8) ? (g_w1h + off) : (g_w2h + off);
    __nv_bfloat16* ol = (m < 8) ? (g_w1l + off) : (g_w2l + off);

    int k0 = blockIdx.y * 32, n0 = blockIdx.x * 32;
    int tx = threadIdx.x, ty0 = threadIdx.y;  // (32, 8)
#pragma unroll
    for (int i = 0; i < 4; i++) {
        int ty = ty0 + i * 8;
        tile[ty][tx] = W[(size_t)(k0 + ty) * 512 + n0 + tx];
    }
    __syncthreads();
#pragma unroll
    for (int i = 0; i < 4; i++) {
        int ty = ty0 + i * 8;
        float v = tile[tx][ty];  // = W[k0+tx][n0+ty]
        __nv_bfloat16 h = __float2bfloat16(v);
        size_t o = (size_t)(n0 + ty) * 512 + (k0 + tx);
        oh[o] = h;
        ol[o] = __float2bfloat16(v - __bfloat162float(h));
    }
}

// ---------------------------------------------------------------------------
// fused gate + split_x + zero-out. 512 blocks x 256 threads; each block
// stages Wg in smem (pitch 9 -> conflict-free), 8 warps x 2 tokens each.
// ---------------------------------------------------------------------------
__global__ void __launch_bounds__(256)
gate_split_kernel(const float* __restrict__ x,
                  const float* __restrict__ Wg,
                  const float* __restrict__ bg,
                  float* __restrict__ out) {
    __shared__ float sWg[512 * 9];
    const int tid  = threadIdx.x;
    const int wid  = tid >> 5;
    const int lane = tid & 31;

    // stage Wg [512][8] into padded smem
#pragma unroll
    for (int i = 0; i < 16; i++) {
        int idx = tid + i * 256;          // 0..4095
        int d = idx >> 3, e = idx & 7;
        sWg[d * 9 + e] = Wg[idx];
    }
    __syncthreads();

#pragma unroll
    for (int k = 0; k < 2; k++) {
        const int tok = blockIdx.x * 16 + wid * 2 + k;
        const float* xr = x + (size_t)tok * DDIM;
        float acc[NEXP];
#pragma unroll
        for (int e = 0; e < NEXP; e++) acc[e] = 0.0f;

#pragma unroll
        for (int i = 0; i < 16; i++) {
            int d = lane + i * 32;
            float xv = xr[d];
            // split store
            __nv_bfloat16 h = __float2bfloat16(xv);
            g_xh[(size_t)tok * DDIM + d] = h;
            g_xl[(size_t)tok * DDIM + d] = __float2bfloat16(xv - __bfloat162float(h));
            out[(size_t)tok * HDIM + d] = 0.0f;
            const float* wr = &sWg[d * 9];
#pragma unroll
            for (int e = 0; e < NEXP; e++) acc[e] += xv * wr[e];
        }
#pragma unroll
        for (int e = 0; e < NEXP; e++)
#pragma unroll
            for (int o = 16; o > 0; o >>= 1)
                acc[e] += __shfl_down_sync(0xffffffffu, acc[e], o);

        if (lane == 0) {
            float s[NEXP];
#pragma unroll
            for (int e = 0; e < NEXP; e++) s[e] = acc[e] + bg[e];
            int i0 = 0;
#pragma unroll
            for (int e = 1; e < NEXP; e++) if (s[e] > s[i0]) i0 = e;
            int i1 = -1;
#pragma unroll
            for (int e = 0; e < NEXP; e++) {
                if (e == i0) continue;
                if (i1 < 0 || s[e] > s[i1]) i1 = e;
            }
            float w0 = 1.0f / (1.0f + expf(s[i1] - s[i0]));
            float w1 = 1.0f - w0;
            int p0 = tok * 2, p1 = tok * 2 + 1;
            int s0 = atomicAdd(&g_cnt[i0], 1); g_list[i0 * NTOK + s0] = p0;
            int s1 = atomicAdd(&g_cnt[i1], 1); g_list[i1 * NTOK + s1] = p1;
            g_w[p0] = w0; g_w[p1] = w1;
        }
    }
}

// ---------------------------------------------------------------------------
// grouped split-bf16 HMMA GEMM (mma.sync m16n8k16).
// CTA tile 128x64, K chunks of 32 (64B rows), 3-stage cp.async pipeline.
// Stage (24KB): Ah(8K)|Al(8K)|Bh(4K)|Bl(4K); 3 stages = 72KB -> 3 CTA/SM.
// 8 warps in 4x2 (M x N); each warp computes 32x32.
// 64B-row swizzle: chunk' = chunk ^ ((row>>1)&3)  (conflict-free ldmatrix).
// ---------------------------------------------------------------------------
#define NCH      16                 // 512 / 32
#define STG_BASE 1024
#define STG_SIZE 24576
#define OFF_AL   8192
#define OFF_BH   16384
#define OFF_BL   20480
#define SMEM_TOT (STG_BASE + 3 * STG_SIZE)

template <bool L2K>
__global__ void __launch_bounds__(256, 3)
moe_hmma_kernel(const float* __restrict__ b1, const float* __restrict__ b2,
                float* __restrict__ out) {
    const int e   = blockIdx.z;
    const int cnt = g_cnt[e];
    const int m0  = blockIdx.y * 128;
    if (m0 >= cnt) return;
    const int n0 = blockIdx.x * 64;

    extern __shared__ char smem[];
    const uint32_t sb = smem_u32(smem);
    int*   sIdx  = (int*)(smem);
    float* sbias = (float*)(smem + 512);

    const int tid  = threadIdx.x;
    const int wid  = tid >> 5;
    const int lane = tid & 31;

    if (tid < 128) sIdx[tid] = (m0 + tid < cnt) ? g_list[e * NTOK + m0 + tid] : -1;
    if (tid < 64)  sbias[tid] = (L2K ? b2 : b1)[e * HDIM + n0 + tid];
    __syncthreads();

    // ---- A fill lanes: row = tid>>1 (0..127), 2 chunks each ----
    const int lrow = tid >> 1;
    const int half = tid & 1;
    const int p    = sIdx[lrow];
    const bool okA = (p >= 0);
    const uint4* arh;
    const uint4* arl;
    {
        size_t ab = okA ? (L2K ? ((size_t)p * HDIM) : ((size_t)(p >> 1) * DDIM)) : 0;
        arh = (const uint4*)((L2K ? g_hh : g_xh) + ab);
        arl = (const uint4*)((L2K ? g_hl : g_xl) + ab);
    }
    // ---- B fill lanes: row = tid>>2 (0..63), 1 chunk ----
    const int brow = tid >> 2;
    const int cb   = tid & 3;
    const size_t bb = ((size_t)e * HDIM + n0 + brow) * 512;
    const uint4* brh = (const uint4*)((L2K ? g_w2h : g_w1h) + bb);
    const uint4* brl = (const uint4*)((L2K ? g_w2l : g_w1l) + bb);

    // swizzled dst offsets (per-thread constants)
    uint32_t swA[2];
#pragma unroll
    for (int i = 0; i < 2; i++) {
        int ca = half * 2 + i;
        swA[i] = (uint32_t)lrow * 64 + (uint32_t)((ca ^ ((lrow >> 1) & 3)) * 16);
    }
    const uint32_t swB = (uint32_t)brow * 64 + (uint32_t)((cb ^ ((brow >> 1) & 3)) * 16);

    // ---- accumulators: warp tile 32x32 ----
    float acc[2][4][4];
#pragma unroll
    for (int mt = 0; mt < 2; mt++)
#pragma unroll
        for (int nt = 0; nt < 4; nt++)
#pragma unroll
            for (int j = 0; j < 4; j++) acc[mt][nt][j] = 0.0f;

    const int wm = wid >> 1;          // 0..3
    const int wn = wid & 1;           // 0..1
    const int lq = lane >> 3;
    const int lr = lane & 7;
    const int aRow0 = wm * 32 + lr + 8 * (lq & 1);
    const int aC    = lq >> 1;
    const int bRow0 = wn * 32 + (lq >> 1) * 8 + lr;
    const int bC    = lq & 1;
    // per-thread constant swizzle nibbles ( (row>>1)&3 invariant under +16 row steps )
    const uint32_t sAx = (uint32_t)((aRow0 >> 1) & 3);
    const uint32_t sBx = (uint32_t)((bRow0 >> 1) & 3);
    uint32_t xoA[2], xoB[2];
#pragma unroll
    for (int b = 0; b < 2; b++) {
        xoA[b] = (uint32_t)(((b * 2 + aC) ^ sAx) * 16);
        xoB[b] = (uint32_t)(((b * 2 + bC) ^ sBx) * 16);
    }
    const uint32_t aBase = (uint32_t)aRow0 * 64;
    const uint32_t bBase = (uint32_t)bRow0 * 64;

    auto fill = [&](int c, int s) {
        uint32_t base = sb + STG_BASE + (uint32_t)s * STG_SIZE;
        int kq = c * 4;
#pragma unroll
        for (int i = 0; i < 2; i++) {
            int ca = half * 2 + i;
            uint32_t d = base + swA[i];
            CP16(d,          arh + kq + ca, okA);
            CP16(d + OFF_AL, arl + kq + ca, okA);
        }
        CP16(base + OFF_BH + swB, brh + kq + cb, true);
        CP16(base + OFF_BL + swB, brl + kq + cb, true);
        CP_COMMIT();
    };

    fill(0, 0);
    fill(1, 1);

    int s = 0;
    for (int c = 0; c < NCH; c++) {
        CP_WAIT(1);
        __syncthreads();
        if (c + 2 < NCH) fill(c + 2, (s + 2 >= 3) ? s - 1 : s + 2);
        else             CP_COMMIT();

        const uint32_t stg = sb + STG_BASE + (uint32_t)s * STG_SIZE;
#pragma unroll
        for (int b = 0; b < 2; b++) {
            uint32_t bh[8], bl[8];
#pragma unroll
            for (int bp = 0; bp < 2; bp++) {
                uint32_t off = bBase + (uint32_t)bp * 1024 + xoB[b];
                LDSM_X4(bh[bp*4+0], bh[bp*4+1], bh[bp*4+2], bh[bp*4+3],
                        stg + OFF_BH + off);
                LDSM_X4(bl[bp*4+0], bl[bp*4+1], bl[bp*4+2], bl[bp*4+3],
                        stg + OFF_BL + off);
            }
#pragma unroll
            for (int mt = 0; mt < 2; mt++) {
                uint32_t ah[4], al[4];
                uint32_t off = aBase + (uint32_t)mt * 1024 + xoA[b];
                LDSM_X4(ah[0], ah[1], ah[2], ah[3], stg + off);
                LDSM_X4(al[0], al[1], al[2], al[3], stg + OFF_AL + off);
#pragma unroll
                for (int nt = 0; nt < 4; nt++) {
                    MMA16816(acc[mt][nt], ah, bh + nt * 2);
                    MMA16816(acc[mt][nt], ah, bl + nt * 2);
                    MMA16816(acc[mt][nt], al, bh + nt * 2);
                }
            }
        }
        s = (s + 1 >= 3) ? 0 : s + 1;
    }

    // ---- epilogue ----
    const int eg  = lane >> 2;
    const int tig = lane & 3;
#pragma unroll
    for (int mt = 0; mt < 2; mt++) {
#pragma unroll
        for (int hrow = 0; hrow < 2; hrow++) {
            const int rl = wm * 32 + mt * 16 + eg + hrow * 8;
            const int pp = sIdx[rl];
            if (pp < 0) continue;
            const float gw = L2K ? g_w[pp] : 0.0f;
#pragma unroll
            for (int nt = 0; nt < 4; nt++) {
                const int cl = wn * 32 + nt * 8 + tig * 2;
                float v0 = acc[mt][nt][hrow * 2 + 0] + sbias[cl];
                float v1 = acc[mt][nt][hrow * 2 + 1] + sbias[cl + 1];
                if (!L2K) {
                    v0 = 0.5f * v0 * (1.0f + erff(v0 * 0.70710678118654752f));
                    v1 = 0.5f * v1 * (1.0f + erff(v1 * 0.70710678118654752f));
                    __nv_bfloat16 h0 = __float2bfloat16(v0);
                    __nv_bfloat16 h1 = __float2bfloat16(v1);
                    __nv_bfloat16 l0 = __float2bfloat16(v0 - __bfloat162float(h0));
                    __nv_bfloat16 l1 = __float2bfloat16(v1 - __bfloat162float(h1));
                    size_t o = (size_t)pp * HDIM + n0 + cl;
                    *(__nv_bfloat162*)(g_hh + o) = __nv_bfloat162(h0, h1);
                    *(__nv_bfloat162*)(g_hl + o) = __nv_bfloat162(l0, l1);
                } else {
                    size_t o = (size_t)(pp >> 1) * HDIM + n0 + cl;
                    atomicAdd(&out[o],     v0 * gw);
                    atomicAdd(&out[o + 1], v1 * gw);
                }
            }
        }
    }
}

// ---------------------------------------------------------------------------
extern "C" void kernel_launch(void* const* d_in, const int* in_sizes, int n_in,
                              void* d_out, int out_size) {
    const float* x  = (const float*)d_in[0];
    const float* Wg = (const float*)d_in[1];
    const float* bg = (const float*)d_in[2];
    const float* W1 = (const float*)d_in[3];
    const float* b1 = (const float*)d_in[4];
    const float* W2 = (const float*)d_in[5];
    const float* b2 = (const float*)d_in[6];
    float* out = (float*)d_out;

    cudaFuncSetAttribute(moe_hmma_kernel<false>,
                         cudaFuncAttributeMaxDynamicSharedMemorySize, SMEM_TOT);
    cudaFuncSetAttribute(moe_hmma_kernel<true>,
                         cudaFuncAttributeMaxDynamicSharedMemorySize, SMEM_TOT);

    prep_w_kernel<<<dim3(16, 16, 16), dim3(32, 8)>>>(W1, W2);   // also zeroes g_cnt
    gate_split_kernel<<<NTOK / 16, 256>>>(x, Wg, bg, out);      // gate + split + zero

    dim3 grid(HDIM / 64, NTOK / 128, NEXP);
    moe_hmma_kernel<false><<<grid, 256, SMEM_TOT>>>(b1, b2, out);
    moe_hmma_kernel<true ><<<grid, 256, SMEM_TOT>>>(b1, b2, out);
}